// round 7
// baseline (speedup 1.0000x reference)
#include <cuda_runtime.h>

// Problem constants
#define PLANE (8*16*128*128)   // floats per [B=8,C=16,H=128,W=128] stream

// Ping-pong stream buffers: [parity][row][stream(right,up,down)]
__device__ float g_buf[2u*4u*3u*(unsigned)PLANE];

// Grid barrier state (generation-based; g_count self-resets each barrier)
__device__ unsigned g_count = 0;
__device__ volatile unsigned g_gen = 0;

// Dynamic smem: input tile + FULL per-cell weight block
//   s_in : 16 ch x 18x18 halo tile                 20736 B
//   s_w  : [ci=48][k=9][co=48] transposed weights  82944 B
#define SMEM_IN_FLOATS (16 * 324)
#define SMEM_W_FLOATS  (48 * 9 * 48)
#define SMEM_TOTAL     ((SMEM_IN_FLOATS + SMEM_W_FLOATS) * 4)

__device__ __forceinline__ float* BUF(int par, int row, int st) {
    return g_buf + (((size_t)par * 4 + row) * 3 + st) * (size_t)PLANE;
}

__device__ __forceinline__ void grid_barrier(unsigned target) {
    __syncthreads();
    if (threadIdx.x == 0) {
        __threadfence();                       // release (+ L1 flush on sm_103a)
        if (atomicAdd(&g_count, 1u) == gridDim.x - 1) {
            g_count = 0;                       // safe: all arrived, none reading
            __threadfence();
            g_gen = target;
        } else {
            while (g_gen != target) __nanosleep(128);
        }
        __threadfence();                       // acquire
    }
    __syncthreads();
}

// Persistent wavefront kernel. Levels f = 2*col + row (0..9). Within a level,
// CTAs are partitioned across the level's cells; each CTA loads its cell's full
// weight block ONCE, then sweeps 16x16 tiles loading only input halos.
// 256 threads = 4 out-channel-groups(12 co) x 64 pixel slots (2x2 px).
__global__ __launch_bounds__(256, 2) void encoder_persistent(
    const float* __restrict__ x, const float* __restrict__ W,
    const float* __restrict__ bias, float* __restrict__ out)
{
    extern __shared__ __align__(16) float smem[];
    float* s_in = smem;                    // SMEM_IN_FLOATS
    float* s_w  = smem + SMEM_IN_FLOATS;   // SMEM_W_FLOATS

    const int tid = threadIdx.x;
    const int cog = tid & 3;
    const int ps  = tid >> 2;
    const int py0 = (ps >> 3) << 1, px0 = (ps & 7) << 1;
    const int cobase = cog * 12;

    unsigned gen = g_gen;   // launch-start generation

    #pragma unroll 1
    for (int lvl = 0; lvl < 10; lvl++) {
        const int c_min = (lvl >= 2) ? ((lvl - 2) >> 1) : 0;
        const int c_hi  = lvl >> 1;
        const int c_max = (c_hi < 3) ? c_hi : 3;
        const int ncells = c_max - c_min + 1;

        // ---- partition CTAs among this level's cells ----
        int cell_sel, local_id, nlocal;
        if (ncells == 2) {
            const int half = gridDim.x >> 1;
            cell_sel = (blockIdx.x >= half) ? 1 : 0;
            local_id = blockIdx.x - cell_sel * half;
            nlocal   = cell_sel ? (gridDim.x - half) : half;
        } else {
            cell_sel = 0; local_id = blockIdx.x; nlocal = gridDim.x;
        }
        const int c = c_min + cell_sel;
        const int r = lvl - 2 * c;
        const int p = c & 1, q = p ^ 1;

        // ---- per-cell input/output pointers (mirrors reference wavefront) ----
        const float *i0, *i1 = nullptr, *i2 = nullptr;
        if (c == 0) {
            i0 = (r == 0) ? x : BUF(p, r - 1, 2);
        } else {
            i0 = BUF(q, r, 0);
            if (r == 0)      i1 = BUF(q, 1, 1);
            else if (r == 3) i1 = BUF(p, 2, 2);
            else { i1 = BUF(q, r + 1, 1); i2 = BUF(p, r - 1, 2); }
        }
        float* oR = (c == 3 && r == 3) ? out : BUF(p, r, 0);
        float* oU = BUF(p, r, 1);
        float* oD = BUF(p, r, 2);
        const float* Wc = W + (size_t)(c * 4 + r) * (48 * 48 * 9);
        const float* bc = bias + (c * 4 + r) * 48;
        const float* srcs[3] = {i0, i1, i2};

        // ---- load FULL weight block for this cell, transposed to [ci][k][co] ----
        // (synced by the first per-chunk __syncthreads below)
        for (int e = tid; e < 48 * 432; e += 256) {
            int co = e / 432; int rr = e - co * 432;
            int ci = rr / 9;  int k  = rr - ci * 9;
            s_w[(ci * 9 + k) * 48 + co] = Wc[(co * 48 + ci) * 9 + k];
        }

        // ---- sweep this CTA's tiles of the cell ----
        #pragma unroll 1
        for (int t = local_id; t < 512; t += nlocal) {
            const int bz  = t >> 6;
            const int gy0 = ((t >> 3) & 7) << 4;
            const int gx0 = (t & 7) << 4;

            unsigned long long acc[6][2][2];
            #pragma unroll
            for (int jp = 0; jp < 6; jp++)
                #pragma unroll
                for (int py = 0; py < 2; py++)
                    #pragma unroll
                    for (int px = 0; px < 2; px++)
                        acc[jp][py][px] = 0ull;

            #pragma unroll 1
            for (int chunk = 0; chunk < 3; chunk++) {
                const float* src = srcs[chunk];
                if (!src) continue;   // zero slot: skip (uniform)

                // input tile (16ch x 18x18, SAME halo) — L2-direct loads
                for (int e = tid; e < 16 * 324; e += 256) {
                    int ci = e / 324; int rr = e - ci * 324;
                    int ty = rr / 18; int tx = rr - ty * 18;
                    int gy = gy0 - 1 + ty, gx = gx0 - 1 + tx;
                    float v = 0.f;
                    if ((unsigned)gy < 128u && (unsigned)gx < 128u)
                        v = __ldcg(&src[((bz * 16 + ci) * 128 + gy) * 128 + gx]);
                    s_in[e] = v;
                }
                __syncthreads();

                #pragma unroll 4
                for (int cil = 0; cil < 16; cil++) {
                    const int ci = chunk * 16 + cil;    // global input channel
                    unsigned long long xp[16];
                    const float* base = &s_in[cil * 324 + py0 * 18 + px0];
                    #pragma unroll
                    for (int dy = 0; dy < 4; dy++)
                        #pragma unroll
                        for (int dx = 0; dx < 4; dx++) {
                            float v = base[dy * 18 + dx];
                            asm("mov.b64 %0, {%1, %1};" : "=l"(xp[dy * 4 + dx]) : "f"(v));
                        }
                    #pragma unroll
                    for (int k = 0; k < 9; k++) {
                        const int ky = k / 3, kx = k - ky * 3;
                        const unsigned long long* wrow =
                            reinterpret_cast<const unsigned long long*>(
                                &s_w[(ci * 9 + k) * 48 + cobase]);
                        #pragma unroll
                        for (int jp = 0; jp < 6; jp++) {
                            unsigned long long w = wrow[jp];   // LDS.64 co-pair
                            #pragma unroll
                            for (int py = 0; py < 2; py++)
                                #pragma unroll
                                for (int px = 0; px < 2; px++)
                                    asm("fma.rn.f32x2 %0, %1, %2, %0;"
                                        : "+l"(acc[jp][py][px])
                                        : "l"(w), "l"(xp[(py + ky) * 4 + (px + kx)]));
                        }
                    }
                }
                __syncthreads();
            }

            // ---- epilogue: bias + relu, split into right/up/down streams ----
            float* outs[3] = {oR, oU, oD};
            #pragma unroll
            for (int jp = 0; jp < 6; jp++) {
                int co0 = cobase + jp * 2;
                float b0 = bc[co0], b1 = bc[co0 + 1];
                int s0 = co0 >> 4, ch0 = co0 & 15;
                #pragma unroll
                for (int py = 0; py < 2; py++)
                    #pragma unroll
                    for (int px = 0; px < 2; px++) {
                        float lo, hi;
                        asm("mov.b64 {%0, %1}, %2;"
                            : "=f"(lo), "=f"(hi) : "l"(acc[jp][py][px]));
                        lo = fmaxf(lo + b0, 0.f);
                        hi = fmaxf(hi + b1, 0.f);
                        int gy = gy0 + py0 + py, gx = gx0 + px0 + px;
                        float* o = outs[s0];
                        o[((bz * 16 + ch0)     * 128 + gy) * 128 + gx] = lo;
                        o[((bz * 16 + ch0 + 1) * 128 + gy) * 128 + gx] = hi;
                    }
            }
        }

        if (lvl < 9) { ++gen; grid_barrier(gen); }
    }
}

extern "C" void kernel_launch(void* const* d_in, const int* in_sizes, int n_in,
                              void* d_out, int out_size)
{
    const float* x = (const float*)d_in[0];            // [8,16,128,128]
    const float* W = (const float*)d_in[1];            // [4,4,48,48,3,3]
    const float* b = (const float*)d_in[2];            // [4,4,48]
    float* out = (float*)d_out;                        // [8,16,128,128]

    // Sized once on the (uncaptured) correctness run; constant thereafter.
    static int nblocks = 0;
    if (!nblocks) {
        cudaFuncSetAttribute(encoder_persistent,
                             cudaFuncAttributeMaxDynamicSharedMemorySize, SMEM_TOTAL);
        int dev = 0; cudaGetDevice(&dev);
        int sms = 0; cudaDeviceGetAttribute(&sms, cudaDevAttrMultiProcessorCount, dev);
        int occ = 0;
        cudaOccupancyMaxActiveBlocksPerMultiprocessor(&occ, encoder_persistent,
                                                      256, SMEM_TOTAL);
        if (occ < 1) occ = 1;
        if (occ > 2) occ = 2;               // 2 CTAs/SM is the design point
        nblocks = sms * occ;                // all CTAs resident -> barrier is safe
    }

    encoder_persistent<<<nblocks, 256, SMEM_TOTAL>>>(x, W, b, out);
}

// round 9
// speedup vs baseline: 1.0774x; 1.0774x over previous
#include <cuda_runtime.h>

// Problem constants
#define PLANE (8*16*128*128)   // floats per [B=8,C=16,H=128,W=128] stream

// Ping-pong stream buffers: [parity][row][stream(right,up,down)]
__device__ float g_buf[2u*4u*3u*(unsigned)PLANE];

// Grid barrier state (generation-based; g_count self-resets each barrier)
__device__ unsigned g_count = 0;
__device__ volatile unsigned g_gen = 0;

// Dynamic smem: input tile + FULL per-cell weight block
//   s_in : 16 ch x 18x18 halo tile                 20736 B
//   s_w  : [ci=48][k=9][co=48] transposed weights  82944 B
#define SMEM_IN_FLOATS (16 * 324)
#define SMEM_W_FLOATS  (48 * 9 * 48)
#define SMEM_TOTAL     ((SMEM_IN_FLOATS + SMEM_W_FLOATS) * 4)

__device__ __forceinline__ float* BUF(int par, int row, int st) {
    return g_buf + (((size_t)par * 4 + row) * 3 + st) * (size_t)PLANE;
}

__device__ __forceinline__ void grid_barrier(unsigned target) {
    __syncthreads();
    if (threadIdx.x == 0) {
        __threadfence();                       // release (+ L1 flush on sm_103a)
        if (atomicAdd(&g_count, 1u) == gridDim.x - 1) {
            g_count = 0;                       // safe: all arrived, none reading
            __threadfence();
            g_gen = target;
        } else {
            while (g_gen != target) __nanosleep(128);
        }
        __threadfence();                       // acquire
    }
    __syncthreads();
}

// Per-level tables: first cell's column, #cells, chunk-count weights of the
// (up to) two cells. Levels f = 2*col + row.
__constant__ int L_cmin[10]  = {0,0,0,0,1,1,2,2,3,3};
__constant__ int L_ncell[10] = {1,1,2,2,2,2,2,2,1,1};
__constant__ int L_w0[10]    = {1,1,1,1,3,2,3,2,3,2};
__constant__ int L_w1[10]    = {0,0,2,3,2,3,2,3,0,0};

// Persistent wavefront kernel. Within a level, CTAs are partitioned across the
// level's cells PROPORTIONAL TO CHUNK COUNT (work-balanced); each CTA loads its
// cell's full weight block once, then sweeps 16x16 tiles loading input halos.
// 256 threads = 4 out-channel-groups(12 co) x 64 pixel slots (2x2 px).
__global__ __launch_bounds__(256, 2) void encoder_persistent(
    const float* __restrict__ x, const float* __restrict__ W,
    const float* __restrict__ bias, float* __restrict__ out)
{
    extern __shared__ __align__(16) float smem[];
    float* s_in = smem;                    // SMEM_IN_FLOATS
    float* s_w  = smem + SMEM_IN_FLOATS;   // SMEM_W_FLOATS

    const int tid = threadIdx.x;
    const int cog = tid & 3;
    const int ps  = tid >> 2;
    const int py0 = (ps >> 3) << 1, px0 = (ps & 7) << 1;
    const int cobase = cog * 12;

    unsigned gen = g_gen;   // launch-start generation

    #pragma unroll 1
    for (int lvl = 0; lvl < 10; lvl++) {
        // ---- work-balanced CTA partition across this level's cells ----
        int cell_sel, local_id, nlocal;
        if (L_ncell[lvl] == 2) {
            const int w0 = L_w0[lvl], wt = w0 + L_w1[lvl];
            const int n0 = (int)(((long long)gridDim.x * w0 + (wt >> 1)) / wt);
            cell_sel = (blockIdx.x >= n0) ? 1 : 0;
            local_id = blockIdx.x - cell_sel * n0;
            nlocal   = cell_sel ? (gridDim.x - n0) : n0;
        } else {
            cell_sel = 0; local_id = blockIdx.x; nlocal = gridDim.x;
        }
        const int c = L_cmin[lvl] + cell_sel;
        const int r = lvl - 2 * c;
        const int p = c & 1, q = p ^ 1;

        // ---- per-cell input/output pointers (mirrors reference wavefront) ----
        const float *i0, *i1 = nullptr, *i2 = nullptr;
        if (c == 0) {
            i0 = (r == 0) ? x : BUF(p, r - 1, 2);
        } else {
            i0 = BUF(q, r, 0);
            if (r == 0)      i1 = BUF(q, 1, 1);
            else if (r == 3) i1 = BUF(p, 2, 2);
            else { i1 = BUF(q, r + 1, 1); i2 = BUF(p, r - 1, 2); }
        }
        float* oR = (c == 3 && r == 3) ? out : BUF(p, r, 0);
        float* oU = BUF(p, r, 1);
        float* oD = BUF(p, r, 2);
        const float* Wc = W + (size_t)(c * 4 + r) * (48 * 48 * 9);
        const float* bc = bias + (c * 4 + r) * 48;
        const float* srcs[3] = {i0, i1, i2};

        // ---- load FULL weight block for this cell, transposed to [ci][k][co] ----
        // (synced by the first per-chunk __syncthreads below)
        for (int e = tid; e < 48 * 432; e += 256) {
            int co = e / 432; int rr = e - co * 432;
            int ci = rr / 9;  int k  = rr - ci * 9;
            s_w[(ci * 9 + k) * 48 + co] = Wc[(co * 48 + ci) * 9 + k];
        }

        // ---- sweep this CTA's tiles of the cell ----
        #pragma unroll 1
        for (int t = local_id; t < 512; t += nlocal) {
            const int bz  = t >> 6;
            const int gy0 = ((t >> 3) & 7) << 4;
            const int gx0 = (t & 7) << 4;

            unsigned long long acc[6][2][2];
            #pragma unroll
            for (int jp = 0; jp < 6; jp++)
                #pragma unroll
                for (int py = 0; py < 2; py++)
                    #pragma unroll
                    for (int px = 0; px < 2; px++)
                        acc[jp][py][px] = 0ull;

            #pragma unroll 1
            for (int chunk = 0; chunk < 3; chunk++) {
                const float* src = srcs[chunk];
                if (!src) continue;   // zero slot: skip (uniform)

                // input tile (16ch x 18x18, SAME halo) — L2-direct loads
                for (int e = tid; e < 16 * 324; e += 256) {
                    int ci = e / 324; int rr = e - ci * 324;
                    int ty = rr / 18; int tx = rr - ty * 18;
                    int gy = gy0 - 1 + ty, gx = gx0 - 1 + tx;
                    float v = 0.f;
                    if ((unsigned)gy < 128u && (unsigned)gx < 128u)
                        v = __ldcg(&src[((bz * 16 + ci) * 128 + gy) * 128 + gx]);
                    s_in[e] = v;
                }
                __syncthreads();

                #pragma unroll 4
                for (int cil = 0; cil < 16; cil++) {
                    const int ci = chunk * 16 + cil;    // global input channel
                    unsigned long long xp[16];
                    const float* base = &s_in[cil * 324 + py0 * 18 + px0];
                    #pragma unroll
                    for (int dy = 0; dy < 4; dy++)
                        #pragma unroll
                        for (int dx = 0; dx < 4; dx++) {
                            float v = base[dy * 18 + dx];
                            asm("mov.b64 %0, {%1, %1};" : "=l"(xp[dy * 4 + dx]) : "f"(v));
                        }
                    #pragma unroll
                    for (int k = 0; k < 9; k++) {
                        const int ky = k / 3, kx = k - ky * 3;
                        const unsigned long long* wrow =
                            reinterpret_cast<const unsigned long long*>(
                                &s_w[(ci * 9 + k) * 48 + cobase]);
                        #pragma unroll
                        for (int jp = 0; jp < 6; jp++) {
                            unsigned long long w = wrow[jp];   // LDS.64 co-pair
                            #pragma unroll
                            for (int py = 0; py < 2; py++)
                                #pragma unroll
                                for (int px = 0; px < 2; px++)
                                    asm("fma.rn.f32x2 %0, %1, %2, %0;"
                                        : "+l"(acc[jp][py][px])
                                        : "l"(w), "l"(xp[(py + ky) * 4 + (px + kx)]));
                        }
                    }
                }
                __syncthreads();
            }

            // ---- epilogue: bias + relu; paired STG.64 over adjacent px ----
            float* outs[3] = {oR, oU, oD};
            #pragma unroll
            for (int jp = 0; jp < 6; jp++) {
                int co0 = cobase + jp * 2;
                float b0 = bc[co0], b1 = bc[co0 + 1];
                int s0 = co0 >> 4, ch0 = co0 & 15;
                float* o = outs[s0];
                #pragma unroll
                for (int py = 0; py < 2; py++) {
                    float lo0, hi0, lo1, hi1;
                    asm("mov.b64 {%0, %1}, %2;" : "=f"(lo0), "=f"(hi0) : "l"(acc[jp][py][0]));
                    asm("mov.b64 {%0, %1}, %2;" : "=f"(lo1), "=f"(hi1) : "l"(acc[jp][py][1]));
                    lo0 = fmaxf(lo0 + b0, 0.f); lo1 = fmaxf(lo1 + b0, 0.f);
                    hi0 = fmaxf(hi0 + b1, 0.f); hi1 = fmaxf(hi1 + b1, 0.f);
                    int gy = gy0 + py0 + py, gx = gx0 + px0;
                    *reinterpret_cast<float2*>(&o[((bz * 16 + ch0)     * 128 + gy) * 128 + gx])
                        = make_float2(lo0, lo1);
                    *reinterpret_cast<float2*>(&o[((bz * 16 + ch0 + 1) * 128 + gy) * 128 + gx])
                        = make_float2(hi0, hi1);
                }
            }
        }

        if (lvl < 9) { ++gen; grid_barrier(gen); }
    }
}

extern "C" void kernel_launch(void* const* d_in, const int* in_sizes, int n_in,
                              void* d_out, int out_size)
{
    const float* x = (const float*)d_in[0];            // [8,16,128,128]
    const float* W = (const float*)d_in[1];            // [4,4,48,48,3,3]
    const float* b = (const float*)d_in[2];            // [4,4,48]
    float* out = (float*)d_out;                        // [8,16,128,128]

    // Sized once on the (uncaptured) correctness run; constant thereafter.
    static int nblocks = 0;
    if (!nblocks) {
        cudaFuncSetAttribute(encoder_persistent,
                             cudaFuncAttributeMaxDynamicSharedMemorySize, SMEM_TOTAL);
        int dev = 0; cudaGetDevice(&dev);
        int sms = 0; cudaDeviceGetAttribute(&sms, cudaDevAttrMultiProcessorCount, dev);
        int occ = 0;
        cudaOccupancyMaxActiveBlocksPerMultiprocessor(&occ, encoder_persistent,
                                                      256, SMEM_TOTAL);
        if (occ < 1) occ = 1;
        if (occ > 2) occ = 2;               // 2 CTAs/SM is the design point
        nblocks = sms * occ;                // all CTAs resident -> barrier is safe
    }

    encoder_persistent<<<nblocks, 256, SMEM_TOTAL>>>(x, W, b, out);
}